// round 9
// baseline (speedup 1.0000x reference)
#include <cuda_runtime.h>

// ResidualEmbedding: per-frame Burg LPC (order 12) residual, sign-modulated embed.
// R9: R7 structure (4 frames/warp, 8 lanes/frame, 20 samples/lane, 64 regs) plus:
//  - reciprocal of den hoisted off the critical chain (MUFU rcp.approx overlaps
//    the next dot+butterfly; r = -2*s*inv_den is one FMUL after the reduction)
//  - 4-accumulator dot products (half the FMA accumulation depth)
//  - per-block Hann window table in shared (removes 20 __cosf per lane)
//  - launch_bounds(256,4) pins regs <= 64 (R8 lesson: occupancy > intra-warp ILP)

namespace {

constexpr int FRAME   = 160;
constexpr int ORDER   = 12;
constexpr int NFRAMES = 4096 * 15;       // 61440
constexpr int WPB     = 8;               // warps per block (32 frames/block)
constexpr int THREADS = WPB * 32;
constexpr int ROW     = 176;             // 12 halo + 160 + 4 pad (floats)
constexpr unsigned FULL = 0xffffffffu;

__device__ __forceinline__ float grp_sum(float v) {
#pragma unroll
    for (int o = 4; o > 0; o >>= 1) v += __shfl_xor_sync(FULL, v, o);
    return v;
}

__device__ __forceinline__ float fast_rcp(float x) {
    float r; asm("rcp.approx.f32 %0, %1;" : "=f"(r) : "f"(x)); return r;
}

__global__ __launch_bounds__(THREADS, 4) void burg_residual_kernel(
    const int*   __restrict__ bits,
    const float* __restrict__ pcm,
    const float* __restrict__ alpha_p,
    float*       __restrict__ out)
{
    const int warp   = threadIdx.x >> 5;
    const int lane   = threadIdx.x & 31;
    const int frame0 = (blockIdx.x * WPB + warp) * 4;   // exact grid
    const int sub    = lane >> 3;        // frame within warp
    const int lh     = lane & 7;         // lane within frame
    const int jb     = 20 * lh;          // my contiguous j-range start

    __shared__ float win[FRAME];
    __shared__ float Xs[WPB][4][ROW];
    float* __restrict__ P = &Xs[warp][sub][0];          // sample j at P[12+j]

    // ---- Hann window once per block: w[j] = 0.5 - 0.5*cos(2*pi*j/159) ----
    if (threadIdx.x < FRAME)
        win[threadIdx.x] =
            0.5f - 0.5f * __cosf((6.283185307179586f / 159.0f) * (float)threadIdx.x);
    __syncthreads();

    // ---- Vectorized load: 20 contiguous samples (5 x LDG.128) ----
    const float* __restrict__ src = pcm + (long long)(frame0 + sub) * FRAME + jb;
    float x[20];
    {
        const float4* s4 = (const float4*)src;
#pragma unroll
        for (int k = 0; k < 5; ++k) {
            const float4 v = s4[k];
            x[4*k] = v.x; x[4*k+1] = v.y; x[4*k+2] = v.z; x[4*k+3] = v.w;
        }
    }
    {   // stash raw samples + zero halo (P[0..11]) for FIR
        float4* Pd = (float4*)(P + 12 + jb);
#pragma unroll
        for (int k = 0; k < 5; ++k)
            Pd[k] = make_float4(x[4*k], x[4*k+1], x[4*k+2], x[4*k+3]);
        if (lh < 3) ((float4*)P)[lh] = make_float4(0.f, 0.f, 0.f, 0.f);
    }

    // ---- Window from table ----
    float xw[20];
    {
        const float4* W = (const float4*)(win + jb);
#pragma unroll
        for (int k = 0; k < 5; ++k) {
            const float4 v = W[k];
            xw[4*k]   = x[4*k]   * v.x;
            xw[4*k+1] = x[4*k+1] * v.y;
            xw[4*k+2] = x[4*k+2] * v.z;
            xw[4*k+3] = x[4*k+3] * v.w;
        }
    }

    // ---- Init: b[j]=xw[j], f[j]=xw[j+1] (valid j<=158); j=159 entries = 0 ----
    float f[20], b[20];
#pragma unroll
    for (int c = 0; c < 20; ++c) b[c] = xw[c];
#pragma unroll
    for (int c = 0; c < 19; ++c) f[c] = xw[c + 1];
    {
        const float nxt = __shfl_sync(FULL, xw[0], lane + 1);
        f[19] = (lh == 7) ? 0.f : nxt;
    }
    if (lh == 7) b[19] = 0.f;

    float den;
    {
        float p0 = 0.f, p1 = 0.f, p2 = 0.f, p3 = 0.f;
#pragma unroll
        for (int c = 0; c < 20; c += 4) {
            p0 = fmaf(f[c],   f[c],   fmaf(b[c],   b[c],   p0));
            p1 = fmaf(f[c+1], f[c+1], fmaf(b[c+1], b[c+1], p1));
            p2 = fmaf(f[c+2], f[c+2], fmaf(b[c+2], b[c+2], p2));
            p3 = fmaf(f[c+3], f[c+3], fmaf(b[c+3], b[c+3], p3));
        }
        den = grp_sum((p0 + p1) + (p2 + p3));
    }
    float inv_den = fast_rcp(den);

    float a[ORDER + 1];
    a[0] = 1.f;
#pragma unroll
    for (int k = 1; k <= ORDER; ++k) a[k] = 0.f;

    // ---- Burg recursion. Invariant at iter i entry: f[j]=b[j]=0 for j>=159-i ----
#pragma unroll
    for (int i = 0; i < ORDER; ++i) {
        float p0 = 0.f, p1 = 0.f, p2 = 0.f, p3 = 0.f;
#pragma unroll
        for (int c = 0; c < 20; c += 4) {
            p0 = fmaf(f[c],   b[c],   p0);
            p1 = fmaf(f[c+1], b[c+1], p1);
            p2 = fmaf(f[c+2], b[c+2], p2);
            p3 = fmaf(f[c+3], b[c+3], p3);
        }
        const float s = grp_sum((p0 + p1) + (p2 + p3));
        const float r = -2.f * s * inv_den;      // inv_den precomputed last iter

        // in-place: f <- f + r*b ; b <- b + r*f_old
#pragma unroll
        for (int c = 0; c < 20; ++c) {
            const float fo = f[c];
            f[c] = fmaf(r, b[c], f[c]);
            b[c] = fmaf(r, fo,   b[c]);
        }

        // den_{i+1} = (1-r^2)*den - b_new[158-i]^2 - f_new[0]^2
        const int jl = 158 - i, Ll = jl / 20, cl = jl % 20;   // compile-time
        const float nf19 = __shfl_sync(FULL, f[0], lane + 1); // for the shift
        const float t0   = __shfl_sync(FULL, f[0], lane & ~7);
        const float ub   = __shfl_sync(FULL, b[cl], (lane & ~7) | Ll);
        den = (1.f - r * r) * den - ub * ub - t0 * t0;
        inv_den = fast_rcp(den);                 // off-chain: overlaps next dot

        // f' = shift-by-1(f); b': zero newly-invalid element
#pragma unroll
        for (int c = 0; c < 19; ++c) f[c] = f[c + 1];
        f[19] = (lh == 7) ? 0.f : nf19;
        if (lh == Ll) b[cl] = 0.f;

        // a[:i+2] += r * reverse(a[:i+2])  -- pairwise in place
#pragma unroll
        for (int k = 0; 2 * k <= i + 1; ++k) {
            const int k2 = i + 1 - k;
            if (k2 == k) {
                a[k] = a[k] + r * a[k];
            } else {
                const float tmp = a[k];
                a[k]  = fmaf(r, a[k2], a[k]);
                a[k2] = fmaf(r, tmp,  a[k2]);
            }
        }
    }

    // ---- FIR on raw samples: 32-float register window (8 x LDS.128) ----
    __syncwarp();   // halo/sample STS visible across the group
    float xf[32];   // X[jb-12 .. jb+19]
    {
        const float4* W = (const float4*)(P + jb);   // = &P[12 + jb - 12]
#pragma unroll
        for (int k = 0; k < 8; ++k) {
            const float4 v = W[k];
            xf[4*k] = v.x; xf[4*k+1] = v.y; xf[4*k+2] = v.z; xf[4*k+3] = v.w;
        }
    }

    const float sgn  = 2.f * (float)__ldg(&bits[frame0 + sub]) - 1.f;
    const float coef = __ldg(alpha_p) * sgn;

    float o[20];
#pragma unroll
    for (int c = 0; c < 20; ++c) {
        float acc = a[0] * xf[12 + c];
#pragma unroll
        for (int k = 1; k <= ORDER; ++k)
            acc = fmaf(a[k], xf[12 + c - k], acc);
        o[c] = fmaf(coef, acc, xf[12 + c]);
    }

    // ---- Vectorized store (5 x STG.128) ----
    float* __restrict__ dst = out + (long long)(frame0 + sub) * FRAME + jb;
    float4* d4 = (float4*)dst;
#pragma unroll
    for (int k = 0; k < 5; ++k)
        d4[k] = make_float4(o[4*k], o[4*k+1], o[4*k+2], o[4*k+3]);
}

} // namespace

extern "C" void kernel_launch(void* const* d_in, const int* in_sizes, int n_in,
                              void* d_out, int out_size)
{
    const int*   bits  = (const int*)  d_in[0];
    const float* pcm   = (const float*)d_in[1];
    const float* alpha = (const float*)d_in[2];
    float*       out   = (float*)d_out;

    const int grid = NFRAMES / (WPB * 4);   // 1920 blocks
    burg_residual_kernel<<<grid, THREADS>>>(bits, pcm, alpha, out);
}

// round 10
// speedup vs baseline: 1.6959x; 1.6959x over previous
#include <cuda_runtime.h>

// ResidualEmbedding: per-frame Burg LPC (order 12) residual, sign-modulated embed.
// R10: exact R7 structure (4 frames/warp, 8 lanes/frame, 20 samples/lane) with
// ONE change: den reciprocal hoisted off the critical chain (rcp.approx at end
// of iter i overlaps iter i+1's dot+butterfly; r = -2*s*inv_den is one FMUL).
// R9 lesson: register cliff at 64 — no forced launch bounds, no extra live state.

namespace {

constexpr int FRAME   = 160;
constexpr int ORDER   = 12;
constexpr int NFRAMES = 4096 * 15;       // 61440
constexpr int WPB     = 8;               // warps per block (32 frames/block)
constexpr int THREADS = WPB * 32;
constexpr int ROW     = 176;             // 12 halo + 160 + 4 pad (floats, 16B-aligned)
constexpr unsigned FULL = 0xffffffffu;

// reduce over each 8-lane group independently (4 frames at once)
__device__ __forceinline__ float grp_sum(float v) {
#pragma unroll
    for (int o = 4; o > 0; o >>= 1) v += __shfl_xor_sync(FULL, v, o);
    return v;
}

__device__ __forceinline__ float fast_rcp(float x) {
    float r; asm("rcp.approx.f32 %0, %1;" : "=f"(r) : "f"(x)); return r;
}

__global__ __launch_bounds__(THREADS) void burg_residual_kernel(
    const int*   __restrict__ bits,
    const float* __restrict__ pcm,
    const float* __restrict__ alpha_p,
    float*       __restrict__ out)
{
    const int warp   = threadIdx.x >> 5;
    const int lane   = threadIdx.x & 31;
    const int frame0 = (blockIdx.x * WPB + warp) * 4;   // exact grid
    const int sub    = lane >> 3;        // frame within warp
    const int lh     = lane & 7;         // lane within frame
    const int jb     = 20 * lh;          // my contiguous j-range start

    __shared__ float Xs[WPB][4][ROW];
    float* __restrict__ P = &Xs[warp][sub][0];          // sample j at P[12+j]

    // ---- Vectorized load: 20 contiguous samples (5 x LDG.128) ----
    const float* __restrict__ src = pcm + (long long)(frame0 + sub) * FRAME + jb;
    float x[20];
    {
        const float4* s4 = (const float4*)src;
#pragma unroll
        for (int k = 0; k < 5; ++k) {
            const float4 v = s4[k];
            x[4*k] = v.x; x[4*k+1] = v.y; x[4*k+2] = v.z; x[4*k+3] = v.w;
        }
    }
    {   // stash raw samples + zero halo (P[0..11]) for FIR
        float4* Pd = (float4*)(P + 12 + jb);
#pragma unroll
        for (int k = 0; k < 5; ++k)
            Pd[k] = make_float4(x[4*k], x[4*k+1], x[4*k+2], x[4*k+3]);
        if (lh < 3) ((float4*)P)[lh] = make_float4(0.f, 0.f, 0.f, 0.f);
    }

    // ---- Window (np.hanning: 0.5 - 0.5*cos(2*pi*j/159)) ----
    float xw[20];
#pragma unroll
    for (int c = 0; c < 20; ++c) {
        const float w = 0.5f - 0.5f * __cosf((6.283185307179586f / 159.0f) * (float)(jb + c));
        xw[c] = x[c] * w;
    }

    // ---- Init: b[j]=xw[j], f[j]=xw[j+1] (valid j<=158); j=159 entries = 0 ----
    float f[20], b[20];
#pragma unroll
    for (int c = 0; c < 20; ++c) b[c] = xw[c];
#pragma unroll
    for (int c = 0; c < 19; ++c) f[c] = xw[c + 1];
    {
        const float nxt = __shfl_sync(FULL, xw[0], lane + 1);
        f[19] = (lh == 7) ? 0.f : nxt;
    }
    if (lh == 7) b[19] = 0.f;

    float den;
    {
        float p0 = 0.f, p1 = 0.f;
#pragma unroll
        for (int c = 0; c < 20; c += 2) {
            p0 = fmaf(f[c],   f[c],   fmaf(b[c],   b[c],   p0));
            p1 = fmaf(f[c+1], f[c+1], fmaf(b[c+1], b[c+1], p1));
        }
        den = grp_sum(p0 + p1);
    }
    float inv_den = fast_rcp(den);

    float a[ORDER + 1];
    a[0] = 1.f;
#pragma unroll
    for (int k = 1; k <= ORDER; ++k) a[k] = 0.f;

    // ---- Burg recursion. Invariant at iter i entry: f[j]=b[j]=0 for j>=159-i ----
#pragma unroll
    for (int i = 0; i < ORDER; ++i) {
        float p0 = 0.f, p1 = 0.f;
#pragma unroll
        for (int c = 0; c < 20; c += 2) {
            p0 = fmaf(f[c],   b[c],   p0);
            p1 = fmaf(f[c+1], b[c+1], p1);
        }
        const float s = grp_sum(p0 + p1);
        const float r = -2.f * s * inv_den;      // inv_den ready since last iter

        // in-place: f <- t = f + r*b ; b <- u = b + r*f_old
#pragma unroll
        for (int c = 0; c < 20; ++c) {
            const float fo = f[c];
            f[c] = fmaf(r, b[c], f[c]);
            b[c] = fmaf(r, fo,   b[c]);
        }

        // den_{i+1} = (1-r^2)*den - b_new[158-i]^2 - f_new[0]^2
        const int jl = 158 - i, Ll = jl / 20, cl = jl % 20;   // compile-time
        const float nf19 = __shfl_sync(FULL, f[0], lane + 1); // for the shift
        const float t0   = __shfl_sync(FULL, f[0], lane & ~7);
        const float ub   = __shfl_sync(FULL, b[cl], (lane & ~7) | Ll);
        den = (1.f - r * r) * den - ub * ub - t0 * t0;
        inv_den = fast_rcp(den);                 // off-chain: overlaps next dot

        // f' = shift-by-1(f); b': zero newly-invalid element
#pragma unroll
        for (int c = 0; c < 19; ++c) f[c] = f[c + 1];
        f[19] = (lh == 7) ? 0.f : nf19;
        if (lh == Ll) b[cl] = 0.f;

        // a[:i+2] += r * reverse(a[:i+2])  -- pairwise in place
#pragma unroll
        for (int k = 0; 2 * k <= i + 1; ++k) {
            const int k2 = i + 1 - k;
            if (k2 == k) {
                a[k] = a[k] + r * a[k];
            } else {
                const float tmp = a[k];
                a[k]  = fmaf(r, a[k2], a[k]);
                a[k2] = fmaf(r, tmp,  a[k2]);
            }
        }
    }

    // ---- FIR on raw samples: 32-float register window (8 x LDS.128) ----
    __syncwarp();   // halo/sample STS visible across the group
    float xf[32];   // X[jb-12 .. jb+19]
    {
        const float4* W = (const float4*)(P + jb);   // = &P[12 + jb - 12]
#pragma unroll
        for (int k = 0; k < 8; ++k) {
            const float4 v = W[k];
            xf[4*k] = v.x; xf[4*k+1] = v.y; xf[4*k+2] = v.z; xf[4*k+3] = v.w;
        }
    }

    const float sgn  = 2.f * (float)__ldg(&bits[frame0 + sub]) - 1.f;
    const float coef = __ldg(alpha_p) * sgn;

    float o[20];
#pragma unroll
    for (int c = 0; c < 20; ++c) {
        float acc = a[0] * xf[12 + c];
#pragma unroll
        for (int k = 1; k <= ORDER; ++k)
            acc = fmaf(a[k], xf[12 + c - k], acc);
        o[c] = fmaf(coef, acc, xf[12 + c]);
    }

    // ---- Vectorized store (5 x STG.128) ----
    float* __restrict__ dst = out + (long long)(frame0 + sub) * FRAME + jb;
    float4* d4 = (float4*)dst;
#pragma unroll
    for (int k = 0; k < 5; ++k)
        d4[k] = make_float4(o[4*k], o[4*k+1], o[4*k+2], o[4*k+3]);
}

} // namespace

extern "C" void kernel_launch(void* const* d_in, const int* in_sizes, int n_in,
                              void* d_out, int out_size)
{
    const int*   bits  = (const int*)  d_in[0];
    const float* pcm   = (const float*)d_in[1];
    const float* alpha = (const float*)d_in[2];
    float*       out   = (float*)d_out;

    const int grid = NFRAMES / (WPB * 4);   // 1920 blocks
    burg_residual_kernel<<<grid, THREADS>>>(bits, pcm, alpha, out);
}